// round 1
// baseline (speedup 1.0000x reference)
#include <cuda_runtime.h>

// ROI pooling (bilinear, half-pixel centers, clamped to crop), matching the
// JAX reference:
//   img:  (1, 1024, 1024, 256) float32, NHWC
//   rois: (1, 300, 4) float32 (x0, y0, w, h) -> cast to int32
//   out:  (1, 300, 7, 7, 256) float32
//
// Memory-bound gather: each (roi, py, px) output reads 4 corner pixel rows of
// 256 contiguous floats and lerps. Vectorized as float4 (64 lanes x 16B).

#define POOL 7
#define IMG_W 1024
#define C4 64          // 256 channels / 4 per float4

__global__ __launch_bounds__(256) void roi_pool_kernel(
    const float4* __restrict__ img4,   // (H*W, 64) float4
    const float4* __restrict__ rois4,  // (300) float4 = (x0,y0,w,h)
    float4* __restrict__ out4)         // (300*49, 64) float4
{
    const int roi = blockIdx.y;
    const int pos = blockIdx.x * 4 + threadIdx.y;   // 0..48
    if (pos >= POOL * POOL) return;
    const int py = pos / POOL;
    const int px = pos - py * POOL;

    // ROI params (broadcast load; same for whole block)
    const float4 rp = __ldg(rois4 + roi);
    const int x0 = (int)rp.x;
    const int y0 = (int)rp.y;
    const int w  = (int)rp.z;
    const int h  = (int)rp.w;

    // Sample coords, exactly as reference: c = (i+0.5)*(size/P) - 0.5, clamped.
    float cy = ((float)py + 0.5f) * ((float)h / (float)POOL) - 0.5f;
    cy = fminf(fmaxf(cy, 0.0f), (float)h - 1.0f);
    float cx = ((float)px + 0.5f) * ((float)w / (float)POOL) - 0.5f;
    cx = fminf(fmaxf(cx, 0.0f), (float)w - 1.0f);

    const int ylo = (int)cy;                 // cy >= 0 -> trunc == floor
    const int xlo = (int)cx;
    const int yhi = min(ylo + 1, h - 1);
    const int xhi = min(xlo + 1, w - 1);
    const float fy = cy - (float)ylo;
    const float fx = cx - (float)xlo;

    const float w00 = (1.0f - fy) * (1.0f - fx);
    const float w01 = (1.0f - fy) * fx;
    const float w10 = fy * (1.0f - fx);
    const float w11 = fy * fx;

    // Absolute pixel base offsets (in float4 units)
    const long r_lo = (long)(y0 + ylo) * IMG_W;
    const long r_hi = (long)(y0 + yhi) * IMG_W;
    const long b00 = (r_lo + (x0 + xlo)) * C4;
    const long b01 = (r_lo + (x0 + xhi)) * C4;
    const long b10 = (r_hi + (x0 + xlo)) * C4;
    const long b11 = (r_hi + (x0 + xhi)) * C4;

    const int c = threadIdx.x;   // 0..63
    const float4 v00 = __ldg(img4 + b00 + c);
    const float4 v01 = __ldg(img4 + b01 + c);
    const float4 v10 = __ldg(img4 + b10 + c);
    const float4 v11 = __ldg(img4 + b11 + c);

    float4 o;
    o.x = v00.x * w00 + v01.x * w01 + v10.x * w10 + v11.x * w11;
    o.y = v00.y * w00 + v01.y * w01 + v10.y * w10 + v11.y * w11;
    o.z = v00.z * w00 + v01.z * w01 + v10.z * w10 + v11.z * w11;
    o.w = v00.w * w00 + v01.w * w01 + v10.w * w10 + v11.w * w11;

    out4[((long)roi * (POOL * POOL) + pos) * C4 + c] = o;
}

extern "C" void kernel_launch(void* const* d_in, const int* in_sizes, int n_in,
                              void* d_out, int out_size)
{
    const float4* img4  = (const float4*)d_in[0];
    const float4* rois4 = (const float4*)d_in[1];
    float4* o4 = (float4*)d_out;

    dim3 block(64, 4, 1);                  // 64 float4-lanes x 4 pool positions
    dim3 grid((POOL * POOL + 3) / 4, 300, 1);  // 13 x 300
    roi_pool_kernel<<<grid, block>>>(img4, rois4, o4);
}

// round 2
// speedup vs baseline: 1.0029x; 1.0029x over previous
#include <cuda_runtime.h>

// ROI pooling (bilinear, half-pixel centers, clamped to crop).
//   img:  (1, 1024, 1024, 256) float32, NHWC
//   rois: (1, 300, 4) float32 (x0, y0, w, h) -> int
//   out:  (1, 300, 7, 7, 256) float32
//
// R2: latency-bound fix. One block = (roi, px); each thread handles 2 pool
// rows (py, py+4) sharing x-coords -> 8 independent LDG.128 in flight
// (MLP=8 vs 4), zero tail waste, less per-position index math.

#define POOL 7
#define IMG_W 1024
#define C4 64          // 256 channels / 4 floats each

__global__ __launch_bounds__(256) void roi_pool_kernel(
    const float4* __restrict__ img4,   // (H*W, 64) float4
    const float4* __restrict__ rois4,  // (300) float4 = (x0,y0,w,h)
    float4* __restrict__ out4)         // (300*49, 64) float4
{
    const int roi = blockIdx.y;
    const int px  = blockIdx.x;        // 0..6
    const int ty  = threadIdx.y;       // 0..3
    const int c   = threadIdx.x;       // 0..63

    const float4 rp = __ldg(rois4 + roi);
    const int x0 = (int)rp.x;
    const int y0 = (int)rp.y;
    const int w  = (int)rp.z;
    const int h  = (int)rp.w;

    // x coords: shared by all py for this block
    float cx = ((float)px + 0.5f) * ((float)w / (float)POOL) - 0.5f;
    cx = fminf(fmaxf(cx, 0.0f), (float)w - 1.0f);
    const int xlo = (int)cx;
    const int xhi = min(xlo + 1, w - 1);
    const float fx = cx - (float)xlo;

    const float hscale = (float)h / (float)POOL;
    const float hmax   = (float)h - 1.0f;

    const int py0 = ty;          // always valid (0..3)
    const int py1 = ty + 4;      // valid if < 7  (ty < 3)
    const bool has1 = (py1 < POOL);

    // --- y coords for both positions ---
    float cy0 = ((float)py0 + 0.5f) * hscale - 0.5f;
    cy0 = fminf(fmaxf(cy0, 0.0f), hmax);
    const int ylo0 = (int)cy0;
    const int yhi0 = min(ylo0 + 1, h - 1);
    const float fy0 = cy0 - (float)ylo0;

    float cy1 = ((float)py1 + 0.5f) * hscale - 0.5f;
    cy1 = fminf(fmaxf(cy1, 0.0f), hmax);
    const int ylo1 = (int)cy1;
    const int yhi1 = min(ylo1 + 1, h - 1);
    const float fy1 = cy1 - (float)ylo1;

    // Base offsets in float4 units (x columns shared)
    const long colL = (long)(x0 + xlo) * C4 + c;
    const long colR = (long)(x0 + xhi) * C4 + c;
    const long rlo0 = (long)(y0 + ylo0) * (IMG_W * C4);
    const long rhi0 = (long)(y0 + yhi0) * (IMG_W * C4);
    const long rlo1 = (long)(y0 + ylo1) * (IMG_W * C4);
    const long rhi1 = (long)(y0 + yhi1) * (IMG_W * C4);

    // --- issue all loads up front (up to 8 outstanding) ---
    const float4 a00 = __ldg(img4 + rlo0 + colL);
    const float4 a01 = __ldg(img4 + rlo0 + colR);
    const float4 a10 = __ldg(img4 + rhi0 + colL);
    const float4 a11 = __ldg(img4 + rhi0 + colR);

    float4 b00, b01, b10, b11;
    if (has1) {
        b00 = __ldg(img4 + rlo1 + colL);
        b01 = __ldg(img4 + rlo1 + colR);
        b10 = __ldg(img4 + rhi1 + colL);
        b11 = __ldg(img4 + rhi1 + colR);
    }

    const float gx = 1.0f - fx;

    {
        const float w00 = (1.0f - fy0) * gx, w01 = (1.0f - fy0) * fx;
        const float w10 = fy0 * gx,          w11 = fy0 * fx;
        float4 o;
        o.x = a00.x * w00 + a01.x * w01 + a10.x * w10 + a11.x * w11;
        o.y = a00.y * w00 + a01.y * w01 + a10.y * w10 + a11.y * w11;
        o.z = a00.z * w00 + a01.z * w01 + a10.z * w10 + a11.z * w11;
        o.w = a00.w * w00 + a01.w * w01 + a10.w * w10 + a11.w * w11;
        out4[((long)roi * (POOL * POOL) + py0 * POOL + px) * C4 + c] = o;
    }

    if (has1) {
        const float w00 = (1.0f - fy1) * gx, w01 = (1.0f - fy1) * fx;
        const float w10 = fy1 * gx,          w11 = fy1 * fx;
        float4 o;
        o.x = b00.x * w00 + b01.x * w01 + b10.x * w10 + b11.x * w11;
        o.y = b00.y * w00 + b01.y * w01 + b10.y * w10 + b11.y * w11;
        o.z = b00.z * w00 + b01.z * w01 + b10.z * w10 + b11.z * w11;
        o.w = b00.w * w00 + b01.w * w01 + b10.w * w10 + b11.w * w11;
        out4[((long)roi * (POOL * POOL) + py1 * POOL + px) * C4 + c] = o;
    }
}

extern "C" void kernel_launch(void* const* d_in, const int* in_sizes, int n_in,
                              void* d_out, int out_size)
{
    const float4* img4  = (const float4*)d_in[0];
    const float4* rois4 = (const float4*)d_in[1];
    float4* o4 = (float4*)d_out;

    dim3 block(64, 4, 1);       // 64 float4-lanes x 4 py-slots
    dim3 grid(POOL, 300, 1);    // px x roi
    roi_pool_kernel<<<grid, block>>>(img4, rois4, o4);
}

// round 3
// speedup vs baseline: 1.0088x; 1.0058x over previous
#include <cuda_runtime.h>

// ROI pooling (bilinear, half-pixel centers, clamped to crop).
//   img:  (1, 1024, 1024, 256) float32, NHWC
//   rois: (1, 300, 4) float32 (x0, y0, w, h) -> int
//   out:  (1, 300, 7, 7, 256) float32
//
// R3: 32-bit address math (regs down, occ up), streaming stores (__stcs) so
// the 15MB/replay output stream doesn't evict the ~59MB L2-resident read
// footprint across graph replays. 8 independent LDG.128 per thread.

#define POOL 7
#define IMG_W 1024
#define C4 64          // 256 channels / 4 floats each

__global__ __launch_bounds__(256) void roi_pool_kernel(
    const float4* __restrict__ img4,   // (H*W, 64) float4
    const float4* __restrict__ rois4,  // (300) float4 = (x0,y0,w,h)
    float4* __restrict__ out4)         // (300*49, 64) float4
{
    const int roi = blockIdx.y;
    const int px  = blockIdx.x;        // 0..6
    const int ty  = threadIdx.y;       // 0..3
    const int c   = threadIdx.x;       // 0..63

    const float4 rp = __ldg(rois4 + roi);
    const int x0 = (int)rp.x;
    const int y0 = (int)rp.y;
    const int w  = (int)rp.z;
    const int h  = (int)rp.w;

    // x coords: shared by all py for this block
    float cx = ((float)px + 0.5f) * ((float)w / (float)POOL) - 0.5f;
    cx = fminf(fmaxf(cx, 0.0f), (float)w - 1.0f);
    const int xlo = (int)cx;
    const int xhi = min(xlo + 1, w - 1);
    const float fx = cx - (float)xlo;

    const float hscale = (float)h / (float)POOL;
    const float hmax   = (float)h - 1.0f;

    const int py0 = ty;          // 0..3, always valid
    const int py1 = ty + 4;      // valid if < 7
    const bool has1 = (py1 < POOL);

    float cy0 = ((float)py0 + 0.5f) * hscale - 0.5f;
    cy0 = fminf(fmaxf(cy0, 0.0f), hmax);
    const int ylo0 = (int)cy0;
    const int yhi0 = min(ylo0 + 1, h - 1);
    const float fy0 = cy0 - (float)ylo0;

    float cy1 = ((float)py1 + 0.5f) * hscale - 0.5f;
    cy1 = fminf(fmaxf(cy1, 0.0f), hmax);
    const int ylo1 = (int)cy1;
    const int yhi1 = min(ylo1 + 1, h - 1);
    const float fy1 = cy1 - (float)ylo1;

    // All offsets in float4 units fit in 32 bits (max 1024*1024*64 = 2^26).
    const unsigned colL = (unsigned)(x0 + xlo) * C4 + c;
    const unsigned colR = (unsigned)(x0 + xhi) * C4 + c;
    const unsigned rlo0 = (unsigned)(y0 + ylo0) * (IMG_W * C4);
    const unsigned rhi0 = (unsigned)(y0 + yhi0) * (IMG_W * C4);
    const unsigned rlo1 = (unsigned)(y0 + ylo1) * (IMG_W * C4);
    const unsigned rhi1 = (unsigned)(y0 + yhi1) * (IMG_W * C4);

    // Issue all loads up front (up to 8 outstanding LDG.128)
    const float4 a00 = __ldg(img4 + rlo0 + colL);
    const float4 a01 = __ldg(img4 + rlo0 + colR);
    const float4 a10 = __ldg(img4 + rhi0 + colL);
    const float4 a11 = __ldg(img4 + rhi0 + colR);

    float4 b00, b01, b10, b11;
    if (has1) {
        b00 = __ldg(img4 + rlo1 + colL);
        b01 = __ldg(img4 + rlo1 + colR);
        b10 = __ldg(img4 + rhi1 + colL);
        b11 = __ldg(img4 + rhi1 + colR);
    }

    const float gx = 1.0f - fx;
    const unsigned obase = ((unsigned)roi * (POOL * POOL)) * C4 + c;

    {
        const float w00 = (1.0f - fy0) * gx, w01 = (1.0f - fy0) * fx;
        const float w10 = fy0 * gx,          w11 = fy0 * fx;
        float4 o;
        o.x = a00.x * w00 + a01.x * w01 + a10.x * w10 + a11.x * w11;
        o.y = a00.y * w00 + a01.y * w01 + a10.y * w10 + a11.y * w11;
        o.z = a00.z * w00 + a01.z * w01 + a10.z * w10 + a11.z * w11;
        o.w = a00.w * w00 + a01.w * w01 + a10.w * w10 + a11.w * w11;
        __stcs(out4 + obase + (unsigned)(py0 * POOL + px) * C4, o);
    }

    if (has1) {
        const float w00 = (1.0f - fy1) * gx, w01 = (1.0f - fy1) * fx;
        const float w10 = fy1 * gx,          w11 = fy1 * fx;
        float4 o;
        o.x = b00.x * w00 + b01.x * w01 + b10.x * w10 + b11.x * w11;
        o.y = b00.y * w00 + b01.y * w01 + b10.y * w10 + b11.y * w11;
        o.z = b00.z * w00 + b01.z * w01 + b10.z * w10 + b11.z * w11;
        o.w = b00.w * w00 + b01.w * w01 + b10.w * w10 + b11.w * w11;
        __stcs(out4 + obase + (unsigned)(py1 * POOL + px) * C4, o);
    }
}

extern "C" void kernel_launch(void* const* d_in, const int* in_sizes, int n_in,
                              void* d_out, int out_size)
{
    const float4* img4  = (const float4*)d_in[0];
    const float4* rois4 = (const float4*)d_in[1];
    float4* o4 = (float4*)d_out;

    dim3 block(64, 4, 1);       // 64 float4-lanes x 4 py-slots
    dim3 grid(POOL, 300, 1);    // px x roi
    roi_pool_kernel<<<grid, block>>>(img4, rois4, o4);
}